// round 7
// baseline (speedup 1.0000x reference)
#include <cuda_runtime.h>
#include <math.h>
#include <cstdint>
#include <cstddef>

#define BQ 2048
#define NT 49
#define CD 384
#define NH 12
#define HD 32
#define MROWS (BQ*NT)        // 100352
#define QKVN (3*CD)          // 1152
#define RPE 512
#define TBL 169
#define LOG_MAX_SCALE 4.60517018598809136804f

__device__ float g_qkv[(size_t)MROWS * QKVN];
__device__ float g_ao[(size_t)MROWS * CD];
__device__ float g_tab[TBL * NH];
__device__ float g_bias[NH * NT * NT];

// ---------------------------------------------------------------------------
__global__ void cpb_mlp_kernel(const float* __restrict__ w1,
                               const float* __restrict__ b1,
                               const float* __restrict__ w2)
{
    int i2 = blockIdx.x;
    int a = i2 / 13, bcol = i2 % 13;
    float vy = (float)(a - 6) * (8.0f / 6.0f);
    float vx = (float)(bcol - 6) * (8.0f / 6.0f);
    float t0 = copysignf(log2f(fabsf(vy) + 1.0f) / 3.0f, vy);
    float t1 = copysignf(log2f(fabsf(vx) + 1.0f) / 3.0f, vx);

    __shared__ float hidden[RPE];
    __shared__ float red[4];
    int tid = threadIdx.x;
    for (int r = tid; r < RPE; r += 128) {
        float hv = t0 * w1[2 * r] + t1 * w1[2 * r + 1] + b1[r];
        hidden[r] = fmaxf(hv, 0.0f);
    }
    __syncthreads();
    for (int h = 0; h < NH; h++) {
        float p = 0.0f;
        for (int r = tid; r < RPE; r += 128) p += hidden[r] * w2[h * RPE + r];
        #pragma unroll
        for (int o = 16; o > 0; o >>= 1) p += __shfl_xor_sync(0xffffffffu, p, o);
        if ((tid & 31) == 0) red[tid >> 5] = p;
        __syncthreads();
        if (tid == 0) g_tab[i2 * NH + h] = red[0] + red[1] + red[2] + red[3];
        __syncthreads();
    }
}

__global__ void bias_expand_kernel()
{
    int t = blockIdx.x * 256 + threadIdx.x;
    if (t >= NH * NT * NT) return;
    int h = t / (NT * NT);
    int ij = t % (NT * NT);
    int i = ij / NT, j = ij % NT;
    int rel = ((i / 7 - j / 7) + 6) * 13 + ((i % 7 - j % 7) + 6);
    float x = g_tab[rel * NH + h];
    g_bias[t] = 16.0f / (1.0f + __expf(-x));
}

// ---------------------------------------------------------------------------
// TF32 tensor-core GEMM, double-buffered DYNAMIC smem (one barrier per K-iter)
// ---------------------------------------------------------------------------
__device__ __forceinline__ uint32_t f2tf32(float f) {
    uint32_t r;
    asm("cvt.rna.tf32.f32 %0, %1;" : "=r"(r) : "f"(f));
    return r;
}

__device__ __forceinline__ void mma1688(float c[4], const uint32_t a[4], const uint32_t b[2]) {
    asm volatile(
        "mma.sync.aligned.m16n8k8.row.col.f32.tf32.tf32.f32 "
        "{%0,%1,%2,%3}, {%4,%5,%6,%7}, {%8,%9}, {%0,%1,%2,%3};"
        : "+f"(c[0]), "+f"(c[1]), "+f"(c[2]), "+f"(c[3])
        : "r"(a[0]), "r"(a[1]), "r"(a[2]), "r"(a[3]), "r"(b[0]), "r"(b[1]));
}

#define GEMM_LDS 36
#define GEMM_STAGE (128 * GEMM_LDS)                     // u32 per buffer
#define GEMM_SMEM_BYTES (4 * GEMM_STAGE * 4)            // A0,A1,B0,B1

template<int NC, int K, int MODE>
__global__ void __launch_bounds__(256) gemm_tf32(
    const float* __restrict__ A, const float* __restrict__ B,
    float* __restrict__ C,
    const float* __restrict__ bias0, const float* __restrict__ bias1)
{
    extern __shared__ uint32_t smem_dyn[];
    uint32_t* Asm = smem_dyn;                  // [2][GEMM_STAGE]
    uint32_t* Bsm = smem_dyn + 2 * GEMM_STAGE; // [2][GEMM_STAGE]

    int tid = threadIdx.x;
    int lane = tid & 31, w = tid >> 5;
    int g = lane >> 2, t4 = lane & 3;
    int warp_m = (w >> 1) * 32;
    int warp_n = (w & 1) * 64;
    int m0 = blockIdx.y * 128;
    int n0 = blockIdx.x * 128;

    int lr = tid >> 3;
    int lc = (tid & 7) * 4;

    const float* Ap = A + (size_t)(m0 + lr) * K + lc;
    const float* Bp = B + (size_t)(n0 + lr) * K + lc;

    float acc[2][8][4];
    #pragma unroll
    for (int mi = 0; mi < 2; mi++)
        #pragma unroll
        for (int ni = 0; ni < 8; ni++)
            #pragma unroll
            for (int q = 0; q < 4; q++) acc[mi][ni][q] = 0.0f;

    float4 ra[4], rb[4];
    #pragma unroll
    for (int p = 0; p < 4; p++) {
        ra[p] = *(const float4*)(Ap + (size_t)(32 * p) * K);
        rb[p] = *(const float4*)(Bp + (size_t)(32 * p) * K);
    }
    #pragma unroll
    for (int p = 0; p < 4; p++) {
        int row = lr + 32 * p;
        uint32_t* as = &Asm[row * GEMM_LDS + lc];
        as[0] = f2tf32(ra[p].x); as[1] = f2tf32(ra[p].y);
        as[2] = f2tf32(ra[p].z); as[3] = f2tf32(ra[p].w);
        uint32_t* bs = &Bsm[row * GEMM_LDS + lc];
        bs[0] = f2tf32(rb[p].x); bs[1] = f2tf32(rb[p].y);
        bs[2] = f2tf32(rb[p].z); bs[3] = f2tf32(rb[p].w);
    }
    __syncthreads();

    int buf = 0;
    for (int k0 = 0; k0 < K; k0 += 32, buf ^= 1) {
        bool more = (k0 + 32 < K);
        if (more) {
            #pragma unroll
            for (int p = 0; p < 4; p++) {
                ra[p] = *(const float4*)(Ap + (size_t)(32 * p) * K + (k0 + 32));
                rb[p] = *(const float4*)(Bp + (size_t)(32 * p) * K + (k0 + 32));
            }
        }

        const uint32_t* Ab = Asm + buf * GEMM_STAGE;
        const uint32_t* Bb = Bsm + buf * GEMM_STAGE;
        #pragma unroll
        for (int kk0 = 0; kk0 < 32; kk0 += 8) {
            uint32_t af[2][4], bf[8][2];
            #pragma unroll
            for (int mi = 0; mi < 2; mi++) {
                int r = warp_m + mi * 16 + g;
                af[mi][0] = Ab[r * GEMM_LDS + kk0 + t4];
                af[mi][1] = Ab[(r + 8) * GEMM_LDS + kk0 + t4];
                af[mi][2] = Ab[r * GEMM_LDS + kk0 + t4 + 4];
                af[mi][3] = Ab[(r + 8) * GEMM_LDS + kk0 + t4 + 4];
            }
            #pragma unroll
            for (int ni = 0; ni < 8; ni++) {
                int c = warp_n + ni * 8 + g;
                bf[ni][0] = Bb[c * GEMM_LDS + kk0 + t4];
                bf[ni][1] = Bb[c * GEMM_LDS + kk0 + t4 + 4];
            }
            #pragma unroll
            for (int mi = 0; mi < 2; mi++)
                #pragma unroll
                for (int ni = 0; ni < 8; ni++)
                    mma1688(acc[mi][ni], af[mi], bf[ni]);
        }

        if (more) {
            uint32_t* An = Asm + (buf ^ 1) * GEMM_STAGE;
            uint32_t* Bn = Bsm + (buf ^ 1) * GEMM_STAGE;
            #pragma unroll
            for (int p = 0; p < 4; p++) {
                int row = lr + 32 * p;
                uint32_t* as = &An[row * GEMM_LDS + lc];
                as[0] = f2tf32(ra[p].x); as[1] = f2tf32(ra[p].y);
                as[2] = f2tf32(ra[p].z); as[3] = f2tf32(ra[p].w);
                uint32_t* bs = &Bn[row * GEMM_LDS + lc];
                bs[0] = f2tf32(rb[p].x); bs[1] = f2tf32(rb[p].y);
                bs[2] = f2tf32(rb[p].z); bs[3] = f2tf32(rb[p].w);
            }
        }
        __syncthreads();
    }

    #pragma unroll
    for (int ni = 0; ni < 8; ni++) {
        int col = n0 + warp_n + ni * 8 + 2 * t4;
        float bx, by;
        if (MODE == 0) {
            bx = (col < CD) ? bias0[col] : ((col < 2 * CD) ? 0.0f : bias1[col - 2 * CD]);
            int c1 = col + 1;
            by = (c1 < CD) ? bias0[c1] : ((c1 < 2 * CD) ? 0.0f : bias1[c1 - 2 * CD]);
        } else {
            bx = bias0[col]; by = bias0[col + 1];
        }
        #pragma unroll
        for (int mi = 0; mi < 2; mi++) {
            int row = m0 + warp_m + mi * 16 + g;
            float2 o0 = make_float2(acc[mi][ni][0] + bx, acc[mi][ni][1] + by);
            float2 o1 = make_float2(acc[mi][ni][2] + bx, acc[mi][ni][3] + by);
            *(float2*)(C + (size_t)row * NC + col) = o0;
            *(float2*)(C + (size_t)(row + 8) * NC + col) = o1;
        }
    }
}

// ---------------------------------------------------------------------------
// Attention (register-blocked) + bias prefetch.
// ---------------------------------------------------------------------------
#define QKP 36
#define PSP 52

__device__ __forceinline__ float dot4(float4 a, float4 b, float acc) {
    acc = fmaf(a.x, b.x, acc); acc = fmaf(a.y, b.y, acc);
    acc = fmaf(a.z, b.z, acc); acc = fmaf(a.w, b.w, acc);
    return acc;
}

__global__ void __launch_bounds__(256, 4) attn_kernel(const float* __restrict__ logit_scale)
{
    int bh = blockIdx.x;
    int b = bh / NH, h = bh % NH;
    __shared__ float qs[NT * QKP];
    __shared__ float ks[NT * QKP];
    __shared__ float vt[HD * PSP];
    __shared__ float ps[NT * PSP];

    int tid = threadIdx.x, lane = tid & 31, warp = tid >> 5;
    float scale = __expf(fminf(logit_scale[h], LOG_MAX_SCALE));

    size_t base = (size_t)(b * NT) * QKVN + (size_t)h * HD;
    for (int idx = tid; idx < NT * 8; idx += 256) {
        int i = idx >> 3, d4 = (idx & 7) * 4;
        size_t off = base + (size_t)i * QKVN + d4;
        float4 qv = *(const float4*)(g_qkv + off);
        float4 kv = *(const float4*)(g_qkv + off + CD);
        float4 vv = *(const float4*)(g_qkv + off + 2 * CD);
        *(float4*)(qs + i * QKP + d4) = qv;
        *(float4*)(ks + i * QKP + d4) = kv;
        vt[(d4 + 0) * PSP + i] = vv.x;
        vt[(d4 + 1) * PSP + i] = vv.y;
        vt[(d4 + 2) * PSP + i] = vv.z;
        vt[(d4 + 3) * PSP + i] = vv.w;
    }
    __syncthreads();

    for (int i = warp; i < NT; i += 8) {
        float qv = qs[i * QKP + lane];
        float s = qv * qv;
        #pragma unroll
        for (int o = 16; o > 0; o >>= 1) s += __shfl_xor_sync(0xffffffffu, s, o);
        qs[i * QKP + lane] = qv * (scale / (sqrtf(s) + 1e-12f));
        float kv = ks[i * QKP + lane];
        float s2 = kv * kv;
        #pragma unroll
        for (int o = 16; o > 0; o >>= 1) s2 += __shfl_xor_sync(0xffffffffu, s2, o);
        ks[i * QKP + lane] = kv / (sqrtf(s2) + 1e-12f);
    }
    __syncthreads();

    // prefetch bias for all 4 row-pairs (overlaps score compute)
    const float* bias_h = g_bias + h * NT * NT;
    float pb0[4], pb1[4], pb2[4], pb3[4];
    #pragma unroll
    for (int p = 0; p < 4; p++) {
        int i0 = warp * 2 + p * 16;
        int ic = (i0 < NT) ? i0 : 0;
        int i1 = (ic + 1 < NT) ? (ic + 1) : ic;
        pb0[p] = __ldg(bias_h + ic * NT + lane);
        pb1[p] = (lane < 17) ? __ldg(bias_h + ic * NT + 32 + lane) : 0.0f;
        pb2[p] = __ldg(bias_h + i1 * NT + lane);
        pb3[p] = (lane < 17) ? __ldg(bias_h + i1 * NT + 32 + lane) : 0.0f;
    }

    // score phase
    int j1 = (lane < 17) ? (lane + 32) : 0;
    float d00[4], d01[4], d10[4], d11[4];
    #pragma unroll
    for (int p = 0; p < 4; p++) { d00[p] = d01[p] = d10[p] = d11[p] = 0.0f; }

    #pragma unroll
    for (int q8 = 0; q8 < HD; q8 += 8) {
        float4 k0a = *(const float4*)(ks + lane * QKP + q8);
        float4 k0b = *(const float4*)(ks + lane * QKP + q8 + 4);
        float4 k1a = *(const float4*)(ks + j1 * QKP + q8);
        float4 k1b = *(const float4*)(ks + j1 * QKP + q8 + 4);
        #pragma unroll
        for (int p = 0; p < 4; p++) {
            int i0 = warp * 2 + p * 16;
            if (i0 >= NT) continue;
            int i1 = (i0 + 1 < NT) ? (i0 + 1) : i0;
            float4 q0a = *(const float4*)(qs + i0 * QKP + q8);
            float4 q0b = *(const float4*)(qs + i0 * QKP + q8 + 4);
            float4 q1a = *(const float4*)(qs + i1 * QKP + q8);
            float4 q1b = *(const float4*)(qs + i1 * QKP + q8 + 4);
            d00[p] = dot4(q0b, k0b, dot4(q0a, k0a, d00[p]));
            d01[p] = dot4(q0b, k1b, dot4(q0a, k1a, d01[p]));
            d10[p] = dot4(q1b, k0b, dot4(q1a, k0a, d10[p]));
            d11[p] = dot4(q1b, k1b, dot4(q1a, k1a, d11[p]));
        }
    }

    // softmax per pair with prefetched bias
    #pragma unroll
    for (int p = 0; p < 4; p++) {
        int i0 = warp * 2 + p * 16;
        if (i0 >= NT) continue;
        bool has1 = (i0 + 1 < NT);
        {
            float s0 = d00[p] + pb0[p];
            float s1 = (lane < 17) ? (d01[p] + pb1[p]) : -INFINITY;
            float m = fmaxf(s0, s1);
            #pragma unroll
            for (int o = 16; o > 0; o >>= 1) m = fmaxf(m, __shfl_xor_sync(0xffffffffu, m, o));
            float e0 = __expf(s0 - m);
            float e1 = (lane < 17) ? __expf(s1 - m) : 0.0f;
            float sum = e0 + e1;
            #pragma unroll
            for (int o = 16; o > 0; o >>= 1) sum += __shfl_xor_sync(0xffffffffu, sum, o);
            float inv = __fdividef(1.0f, sum);
            ps[i0 * PSP + lane] = e0 * inv;
            if (lane < 17) ps[i0 * PSP + 32 + lane] = e1 * inv;
        }
        if (has1) {
            int i1 = i0 + 1;
            float s0 = d10[p] + pb2[p];
            float s1 = (lane < 17) ? (d11[p] + pb3[p]) : -INFINITY;
            float m = fmaxf(s0, s1);
            #pragma unroll
            for (int o = 16; o > 0; o >>= 1) m = fmaxf(m, __shfl_xor_sync(0xffffffffu, m, o));
            float e0 = __expf(s0 - m);
            float e1 = (lane < 17) ? __expf(s1 - m) : 0.0f;
            float sum = e0 + e1;
            #pragma unroll
            for (int o = 16; o > 0; o >>= 1) sum += __shfl_xor_sync(0xffffffffu, sum, o);
            float inv = __fdividef(1.0f, sum);
            ps[i1 * PSP + lane] = e0 * inv;
            if (lane < 17) ps[i1 * PSP + 32 + lane] = e1 * inv;
        }
    }
    __syncthreads();

    // PV phase
    float a0[4], a1[4];
    #pragma unroll
    for (int p = 0; p < 4; p++) { a0[p] = a1[p] = 0.0f; }

    #pragma unroll
    for (int jc = 0; jc < 48; jc += 16) {
        float4 v0 = *(const float4*)(vt + lane * PSP + jc);
        float4 v1 = *(const float4*)(vt + lane * PSP + jc + 4);
        float4 v2 = *(const float4*)(vt + lane * PSP + jc + 8);
        float4 v3 = *(const float4*)(vt + lane * PSP + jc + 12);
        #pragma unroll
        for (int p = 0; p < 4; p++) {
            int i0 = warp * 2 + p * 16;
            if (i0 >= NT) continue;
            int i1 = (i0 + 1 < NT) ? (i0 + 1) : i0;
            float4 p00 = *(const float4*)(ps + i0 * PSP + jc);
            float4 p01 = *(const float4*)(ps + i0 * PSP + jc + 4);
            float4 p02 = *(const float4*)(ps + i0 * PSP + jc + 8);
            float4 p03 = *(const float4*)(ps + i0 * PSP + jc + 12);
            a0[p] = dot4(p03, v3, dot4(p02, v2, dot4(p01, v1, dot4(p00, v0, a0[p]))));
            float4 p10 = *(const float4*)(ps + i1 * PSP + jc);
            float4 p11 = *(const float4*)(ps + i1 * PSP + jc + 4);
            float4 p12 = *(const float4*)(ps + i1 * PSP + jc + 8);
            float4 p13 = *(const float4*)(ps + i1 * PSP + jc + 12);
            a1[p] = dot4(p13, v3, dot4(p12, v2, dot4(p11, v1, dot4(p10, v0, a1[p]))));
        }
    }
    {
        float vv = vt[lane * PSP + 48];
        #pragma unroll
        for (int p = 0; p < 4; p++) {
            int i0 = warp * 2 + p * 16;
            if (i0 >= NT) continue;
            bool has1 = (i0 + 1 < NT);
            int i1 = has1 ? (i0 + 1) : i0;
            a0[p] = fmaf(ps[i0 * PSP + 48], vv, a0[p]);
            a1[p] = fmaf(ps[i1 * PSP + 48], vv, a1[p]);
            g_ao[(size_t)(b * NT + i0) * CD + h * HD + lane] = a0[p];
            if (has1)
                g_ao[(size_t)(b * NT + i1) * CD + h * HD + lane] = a1[p];
        }
    }
}

// ---------------------------------------------------------------------------
extern "C" void kernel_launch(void* const* d_in, const int* in_sizes, int n_in,
                              void* d_out, int out_size)
{
    const float* x           = (const float*)d_in[0];
    const float* qkv_w       = (const float*)d_in[1];
    const float* q_bias      = (const float*)d_in[2];
    const float* v_bias      = (const float*)d_in[3];
    const float* logit_scale = (const float*)d_in[4];
    const float* cpb_w1      = (const float*)d_in[5];
    const float* cpb_b1      = (const float*)d_in[6];
    const float* cpb_w2      = (const float*)d_in[7];
    const float* proj_w      = (const float*)d_in[8];
    const float* proj_b      = (const float*)d_in[9];
    float* out = (float*)d_out;

    void* p;
    cudaGetSymbolAddress(&p, g_qkv); float* qkv = (float*)p;
    cudaGetSymbolAddress(&p, g_ao);  float* ao  = (float*)p;

    // opt in to >48KB dynamic smem (host-side, capture-safe, no allocation)
    static bool attr_set = false;
    if (!attr_set) {
        cudaFuncSetAttribute(gemm_tf32<QKVN, CD, 0>,
                             cudaFuncAttributeMaxDynamicSharedMemorySize, GEMM_SMEM_BYTES);
        cudaFuncSetAttribute(gemm_tf32<CD, CD, 1>,
                             cudaFuncAttributeMaxDynamicSharedMemorySize, GEMM_SMEM_BYTES);
        attr_set = true;
    }

    cpb_mlp_kernel<<<TBL, 128>>>(cpb_w1, cpb_b1, cpb_w2);
    bias_expand_kernel<<<(NH * NT * NT + 255) / 256, 256>>>();

    dim3 gq(QKVN / 128, MROWS / 128);
    gemm_tf32<QKVN, CD, 0><<<gq, 256, GEMM_SMEM_BYTES>>>(x, qkv_w, qkv, q_bias, v_bias);

    attn_kernel<<<BQ * NH, 256>>>(logit_scale);

    dim3 gp(CD / 128, MROWS / 128);
    gemm_tf32<CD, CD, 1><<<gp, 256, GEMM_SMEM_BYTES>>>(ao, proj_w, out, proj_b, nullptr);
}

// round 9
// speedup vs baseline: 1.1821x; 1.1821x over previous
#include <cuda_runtime.h>
#include <cuda_fp16.h>
#include <math.h>
#include <cstdint>
#include <cstddef>

#define BQ 2048
#define NT 49
#define CD 384
#define NH 12
#define HD 32
#define MROWS (BQ*NT)        // 100352
#define QKVN (3*CD)          // 1152
#define RPE 512
#define TBL 169
#define LOG_MAX_SCALE 4.60517018598809136804f

__device__ float g_qkv[(size_t)MROWS * QKVN];
__device__ float g_ao[(size_t)MROWS * CD];
__device__ float g_tab[TBL * NH];
__device__ float g_bias[NH * NT * NT];

// ---------------------------------------------------------------------------
__global__ void cpb_mlp_kernel(const float* __restrict__ w1,
                               const float* __restrict__ b1,
                               const float* __restrict__ w2)
{
    int i2 = blockIdx.x;
    int a = i2 / 13, bcol = i2 % 13;
    float vy = (float)(a - 6) * (8.0f / 6.0f);
    float vx = (float)(bcol - 6) * (8.0f / 6.0f);
    float t0 = copysignf(log2f(fabsf(vy) + 1.0f) / 3.0f, vy);
    float t1 = copysignf(log2f(fabsf(vx) + 1.0f) / 3.0f, vx);

    __shared__ float hidden[RPE];
    __shared__ float red[4];
    int tid = threadIdx.x;
    for (int r = tid; r < RPE; r += 128) {
        float hv = t0 * w1[2 * r] + t1 * w1[2 * r + 1] + b1[r];
        hidden[r] = fmaxf(hv, 0.0f);
    }
    __syncthreads();
    for (int h = 0; h < NH; h++) {
        float p = 0.0f;
        for (int r = tid; r < RPE; r += 128) p += hidden[r] * w2[h * RPE + r];
        #pragma unroll
        for (int o = 16; o > 0; o >>= 1) p += __shfl_xor_sync(0xffffffffu, p, o);
        if ((tid & 31) == 0) red[tid >> 5] = p;
        __syncthreads();
        if (tid == 0) g_tab[i2 * NH + h] = red[0] + red[1] + red[2] + red[3];
        __syncthreads();
    }
}

__global__ void bias_expand_kernel()
{
    int t = blockIdx.x * 256 + threadIdx.x;
    if (t >= NH * NT * NT) return;
    int h = t / (NT * NT);
    int ij = t % (NT * NT);
    int i = ij / NT, j = ij % NT;
    int rel = ((i / 7 - j / 7) + 6) * 13 + ((i % 7 - j % 7) + 6);
    float x = g_tab[rel * NH + h];
    g_bias[t] = 16.0f / (1.0f + __expf(-x));
}

// ---------------------------------------------------------------------------
// FP16 tensor-core GEMM (mma.sync m16n8k16, f32 accumulate).
// C[M,NC] = A[M,384] @ B[NC,384]^T + bias. 128x128 CTA tile, BK=32,
// smem fp16 rows stride 40 halves (80B) -> conflict-free ldmatrix.
// ---------------------------------------------------------------------------
__device__ __forceinline__ uint32_t smem_u32(const void* p) {
    uint32_t a;
    asm("{ .reg .u64 t; cvta.to.shared.u64 t, %1; cvt.u32.u64 %0, t; }"
        : "=r"(a) : "l"(p));
    return a;
}

__device__ __forceinline__ uint2 pack4h(float4 v) {
    __half2 h0 = __floats2half2_rn(v.x, v.y);
    __half2 h1 = __floats2half2_rn(v.z, v.w);
    uint2 r;
    r.x = *(uint32_t*)&h0;
    r.y = *(uint32_t*)&h1;
    return r;
}

#define LDSM4(r0, r1, r2, r3, a) \
    asm volatile("ldmatrix.sync.aligned.m8n8.x4.shared.b16 {%0,%1,%2,%3}, [%4];" \
                 : "=r"(r0), "=r"(r1), "=r"(r2), "=r"(r3) : "r"(a))

__device__ __forceinline__ void mma_fp16(float c[4], uint32_t a0, uint32_t a1,
                                         uint32_t a2, uint32_t a3,
                                         uint32_t b0, uint32_t b1) {
    asm volatile(
        "mma.sync.aligned.m16n8k16.row.col.f32.f16.f16.f32 "
        "{%0,%1,%2,%3}, {%4,%5,%6,%7}, {%8,%9}, {%0,%1,%2,%3};"
        : "+f"(c[0]), "+f"(c[1]), "+f"(c[2]), "+f"(c[3])
        : "r"(a0), "r"(a1), "r"(a2), "r"(a3), "r"(b0), "r"(b1));
}

#define HROW 40   // halves per smem row (32 data + 8 pad); 80 bytes

template<int NC, int MODE>
__global__ void __launch_bounds__(256, 2) gemm_fp16(
    const float* __restrict__ A, const float* __restrict__ B,
    float* __restrict__ C,
    const float* __restrict__ bias0, const float* __restrict__ bias1)
{
    constexpr int K = 384;
    __shared__ __align__(16) uint16_t As[128 * HROW];
    __shared__ __align__(16) uint16_t Bs[128 * HROW];

    int tid = threadIdx.x;
    int lane = tid & 31, w = tid >> 5;
    int g = lane >> 2, t4 = lane & 3;
    int warp_m = (w >> 1) * 32;     // 0,32,64,96
    int warp_n = (w & 1) * 64;      // 0,64
    int m0 = blockIdx.y * 128;
    int n0 = blockIdx.x * 128;

    // ldmatrix per-lane source addresses (byte offsets)
    uint32_t as_u = smem_u32(As), bs_u = smem_u32(Bs);
    // A: matrix = lane>>3: {row+0/k0, row+8/k0, row+0/k8, row+8/k8}
    int arow = warp_m + ((lane >> 3) & 1) * 8 + (lane & 7);
    uint32_t aaddr = as_u + arow * 80 + (lane >> 4) * 16;       // + mi*1280 + kk*2
    // B: matrix = lane>>3: {n+0/k0, n+0/k8, n+8/k0, n+8/k8}
    int brow = warp_n + ((lane >> 4) & 1) * 8 + (lane & 7);
    uint32_t baddr = bs_u + brow * 80 + ((lane >> 3) & 1) * 16; // + p*1280 + kk*2

    int lr = tid >> 3;          // 0..31
    int lc = (tid & 7) * 4;     // 0..28

    const float* Ap = A + (size_t)(m0 + lr) * K + lc;
    const float* Bp = B + (size_t)(n0 + lr) * K + lc;

    float acc[2][8][4];
    #pragma unroll
    for (int mi = 0; mi < 2; mi++)
        #pragma unroll
        for (int ni = 0; ni < 8; ni++)
            #pragma unroll
            for (int q = 0; q < 4; q++) acc[mi][ni][q] = 0.0f;

    uint2 ra[4], rb[4];
    #pragma unroll
    for (int p = 0; p < 4; p++) {
        ra[p] = pack4h(*(const float4*)(Ap + (size_t)(32 * p) * K));
        rb[p] = pack4h(*(const float4*)(Bp + (size_t)(32 * p) * K));
    }

    for (int k0 = 0; k0 < K; k0 += 32) {
        #pragma unroll
        for (int p = 0; p < 4; p++) {
            int row = lr + 32 * p;
            *(uint2*)(As + row * HROW + lc) = ra[p];
            *(uint2*)(Bs + row * HROW + lc) = rb[p];
        }
        __syncthreads();

        if (k0 + 32 < K) {
            #pragma unroll
            for (int p = 0; p < 4; p++) {
                ra[p] = pack4h(*(const float4*)(Ap + (size_t)(32 * p) * K + (k0 + 32)));
                rb[p] = pack4h(*(const float4*)(Bp + (size_t)(32 * p) * K + (k0 + 32)));
            }
        }

        #pragma unroll
        for (int kk = 0; kk < 2; kk++) {          // two k16 steps per stage
            uint32_t kb = kk * 32;                // byte offset (16 halves)
            uint32_t af[2][4], bq[4][4];
            #pragma unroll
            for (int mi = 0; mi < 2; mi++)
                LDSM4(af[mi][0], af[mi][1], af[mi][2], af[mi][3],
                      aaddr + mi * 1280 + kb);
            #pragma unroll
            for (int p = 0; p < 4; p++)
                LDSM4(bq[p][0], bq[p][1], bq[p][2], bq[p][3],
                      baddr + p * 1280 + kb);
            #pragma unroll
            for (int mi = 0; mi < 2; mi++)
                #pragma unroll
                for (int ni = 0; ni < 8; ni++) {
                    int p = ni >> 1, hsel = (ni & 1) * 2;
                    mma_fp16(acc[mi][ni], af[mi][0], af[mi][1], af[mi][2], af[mi][3],
                             bq[p][hsel], bq[p][hsel + 1]);
                }
        }
        __syncthreads();
    }

    #pragma unroll
    for (int ni = 0; ni < 8; ni++) {
        int col = n0 + warp_n + ni * 8 + 2 * t4;
        float bx, by;
        if (MODE == 0) {
            bx = (col < CD) ? bias0[col] : ((col < 2 * CD) ? 0.0f : bias1[col - 2 * CD]);
            int c1 = col + 1;
            by = (c1 < CD) ? bias0[c1] : ((c1 < 2 * CD) ? 0.0f : bias1[c1 - 2 * CD]);
        } else {
            bx = bias0[col]; by = bias0[col + 1];
        }
        #pragma unroll
        for (int mi = 0; mi < 2; mi++) {
            int row = m0 + warp_m + mi * 16 + g;
            float2 o0 = make_float2(acc[mi][ni][0] + bx, acc[mi][ni][1] + by);
            float2 o1 = make_float2(acc[mi][ni][2] + bx, acc[mi][ni][3] + by);
            *(float2*)(C + (size_t)row * NC + col) = o0;
            *(float2*)(C + (size_t)(row + 8) * NC + col) = o1;
        }
    }
}

// ---------------------------------------------------------------------------
// Attention (round-5 register-blocked version; best measured)
// ---------------------------------------------------------------------------
#define QKP 36
#define PSP 52

__device__ __forceinline__ float dot4(float4 a, float4 b, float acc) {
    acc = fmaf(a.x, b.x, acc); acc = fmaf(a.y, b.y, acc);
    acc = fmaf(a.z, b.z, acc); acc = fmaf(a.w, b.w, acc);
    return acc;
}

__global__ void __launch_bounds__(256, 4) attn_kernel(const float* __restrict__ logit_scale)
{
    int bh = blockIdx.x;
    int b = bh / NH, h = bh % NH;
    __shared__ float qs[NT * QKP];
    __shared__ float ks[NT * QKP];
    __shared__ float vt[HD * PSP];
    __shared__ float ps[NT * PSP];

    int tid = threadIdx.x, lane = tid & 31, warp = tid >> 5;
    float scale = __expf(fminf(logit_scale[h], LOG_MAX_SCALE));

    size_t base = (size_t)(b * NT) * QKVN + (size_t)h * HD;
    for (int idx = tid; idx < NT * 8; idx += 256) {
        int i = idx >> 3, d4 = (idx & 7) * 4;
        size_t off = base + (size_t)i * QKVN + d4;
        float4 qv = *(const float4*)(g_qkv + off);
        float4 kv = *(const float4*)(g_qkv + off + CD);
        float4 vv = *(const float4*)(g_qkv + off + 2 * CD);
        *(float4*)(qs + i * QKP + d4) = qv;
        *(float4*)(ks + i * QKP + d4) = kv;
        vt[(d4 + 0) * PSP + i] = vv.x;
        vt[(d4 + 1) * PSP + i] = vv.y;
        vt[(d4 + 2) * PSP + i] = vv.z;
        vt[(d4 + 3) * PSP + i] = vv.w;
    }
    __syncthreads();

    for (int i = warp; i < NT; i += 8) {
        float qv = qs[i * QKP + lane];
        float s = qv * qv;
        #pragma unroll
        for (int o = 16; o > 0; o >>= 1) s += __shfl_xor_sync(0xffffffffu, s, o);
        qs[i * QKP + lane] = qv * (scale / (sqrtf(s) + 1e-12f));
        float kv = ks[i * QKP + lane];
        float s2 = kv * kv;
        #pragma unroll
        for (int o = 16; o > 0; o >>= 1) s2 += __shfl_xor_sync(0xffffffffu, s2, o);
        ks[i * QKP + lane] = kv / (sqrtf(s2) + 1e-12f);
    }
    __syncthreads();

    int j1 = (lane < 17) ? (lane + 32) : 0;
    float d00[4], d01[4], d10[4], d11[4];
    #pragma unroll
    for (int p = 0; p < 4; p++) { d00[p] = d01[p] = d10[p] = d11[p] = 0.0f; }

    #pragma unroll
    for (int q8 = 0; q8 < HD; q8 += 8) {
        float4 k0a = *(const float4*)(ks + lane * QKP + q8);
        float4 k0b = *(const float4*)(ks + lane * QKP + q8 + 4);
        float4 k1a = *(const float4*)(ks + j1 * QKP + q8);
        float4 k1b = *(const float4*)(ks + j1 * QKP + q8 + 4);
        #pragma unroll
        for (int p = 0; p < 4; p++) {
            int i0 = warp * 2 + p * 16;
            if (i0 >= NT) continue;
            int i1 = (i0 + 1 < NT) ? (i0 + 1) : i0;
            float4 q0a = *(const float4*)(qs + i0 * QKP + q8);
            float4 q0b = *(const float4*)(qs + i0 * QKP + q8 + 4);
            float4 q1a = *(const float4*)(qs + i1 * QKP + q8);
            float4 q1b = *(const float4*)(qs + i1 * QKP + q8 + 4);
            d00[p] = dot4(q0b, k0b, dot4(q0a, k0a, d00[p]));
            d01[p] = dot4(q0b, k1b, dot4(q0a, k1a, d01[p]));
            d10[p] = dot4(q1b, k0b, dot4(q1a, k0a, d10[p]));
            d11[p] = dot4(q1b, k1b, dot4(q1a, k1a, d11[p]));
        }
    }

    const float* bias_h = g_bias + h * NT * NT;
    #pragma unroll
    for (int p = 0; p < 4; p++) {
        int i0 = warp * 2 + p * 16;
        if (i0 >= NT) continue;
        bool has1 = (i0 + 1 < NT);
        {
            float s0 = d00[p] + __ldg(bias_h + i0 * NT + lane);
            float s1 = (lane < 17) ? (d01[p] + __ldg(bias_h + i0 * NT + 32 + lane)) : -INFINITY;
            float m = fmaxf(s0, s1);
            #pragma unroll
            for (int o = 16; o > 0; o >>= 1) m = fmaxf(m, __shfl_xor_sync(0xffffffffu, m, o));
            float e0 = __expf(s0 - m);
            float e1 = (lane < 17) ? __expf(s1 - m) : 0.0f;
            float sum = e0 + e1;
            #pragma unroll
            for (int o = 16; o > 0; o >>= 1) sum += __shfl_xor_sync(0xffffffffu, sum, o);
            float inv = __fdividef(1.0f, sum);
            ps[i0 * PSP + lane] = e0 * inv;
            if (lane < 17) ps[i0 * PSP + 32 + lane] = e1 * inv;
        }
        if (has1) {
            int i1 = i0 + 1;
            float s0 = d10[p] + __ldg(bias_h + i1 * NT + lane);
            float s1 = (lane < 17) ? (d11[p] + __ldg(bias_h + i1 * NT + 32 + lane)) : -INFINITY;
            float m = fmaxf(s0, s1);
            #pragma unroll
            for (int o = 16; o > 0; o >>= 1) m = fmaxf(m, __shfl_xor_sync(0xffffffffu, m, o));
            float e0 = __expf(s0 - m);
            float e1 = (lane < 17) ? __expf(s1 - m) : 0.0f;
            float sum = e0 + e1;
            #pragma unroll
            for (int o = 16; o > 0; o >>= 1) sum += __shfl_xor_sync(0xffffffffu, sum, o);
            float inv = __fdividef(1.0f, sum);
            ps[i1 * PSP + lane] = e0 * inv;
            if (lane < 17) ps[i1 * PSP + 32 + lane] = e1 * inv;
        }
    }
    __syncthreads();

    float a0[4], a1[4];
    #pragma unroll
    for (int p = 0; p < 4; p++) { a0[p] = a1[p] = 0.0f; }

    #pragma unroll
    for (int jc = 0; jc < 48; jc += 16) {
        float4 v0 = *(const float4*)(vt + lane * PSP + jc);
        float4 v1 = *(const float4*)(vt + lane * PSP + jc + 4);
        float4 v2 = *(const float4*)(vt + lane * PSP + jc + 8);
        float4 v3 = *(const float4*)(vt + lane * PSP + jc + 12);
        #pragma unroll
        for (int p = 0; p < 4; p++) {
            int i0 = warp * 2 + p * 16;
            if (i0 >= NT) continue;
            int i1 = (i0 + 1 < NT) ? (i0 + 1) : i0;
            float4 p00 = *(const float4*)(ps + i0 * PSP + jc);
            float4 p01 = *(const float4*)(ps + i0 * PSP + jc + 4);
            float4 p02 = *(const float4*)(ps + i0 * PSP + jc + 8);
            float4 p03 = *(const float4*)(ps + i0 * PSP + jc + 12);
            a0[p] = dot4(p03, v3, dot4(p02, v2, dot4(p01, v1, dot4(p00, v0, a0[p]))));
            float4 p10 = *(const float4*)(ps + i1 * PSP + jc);
            float4 p11 = *(const float4*)(ps + i1 * PSP + jc + 4);
            float4 p12 = *(const float4*)(ps + i1 * PSP + jc + 8);
            float4 p13 = *(const float4*)(ps + i1 * PSP + jc + 12);
            a1[p] = dot4(p13, v3, dot4(p12, v2, dot4(p11, v1, dot4(p10, v0, a1[p]))));
        }
    }
    {
        float vv = vt[lane * PSP + 48];
        #pragma unroll
        for (int p = 0; p < 4; p++) {
            int i0 = warp * 2 + p * 16;
            if (i0 >= NT) continue;
            bool has1 = (i0 + 1 < NT);
            int i1 = has1 ? (i0 + 1) : i0;
            a0[p] = fmaf(ps[i0 * PSP + 48], vv, a0[p]);
            a1[p] = fmaf(ps[i1 * PSP + 48], vv, a1[p]);
            g_ao[(size_t)(b * NT + i0) * CD + h * HD + lane] = a0[p];
            if (has1)
                g_ao[(size_t)(b * NT + i1) * CD + h * HD + lane] = a1[p];
        }
    }
}

// ---------------------------------------------------------------------------
extern "C" void kernel_launch(void* const* d_in, const int* in_sizes, int n_in,
                              void* d_out, int out_size)
{
    const float* x           = (const float*)d_in[0];
    const float* qkv_w       = (const float*)d_in[1];
    const float* q_bias      = (const float*)d_in[2];
    const float* v_bias      = (const float*)d_in[3];
    const float* logit_scale = (const float*)d_in[4];
    const float* cpb_w1      = (const float*)d_in[5];
    const float* cpb_b1      = (const float*)d_in[6];
    const float* cpb_w2      = (const float*)d_in[7];
    const float* proj_w      = (const float*)d_in[8];
    const float* proj_b      = (const float*)d_in[9];
    float* out = (float*)d_out;

    void* p;
    cudaGetSymbolAddress(&p, g_qkv); float* qkv = (float*)p;
    cudaGetSymbolAddress(&p, g_ao);  float* ao  = (float*)p;

    cpb_mlp_kernel<<<TBL, 128>>>(cpb_w1, cpb_b1, cpb_w2);
    bias_expand_kernel<<<(NH * NT * NT + 255) / 256, 256>>>();

    dim3 gq(QKVN / 128, MROWS / 128);
    gemm_fp16<QKVN, 0><<<gq, 256>>>(x, qkv_w, qkv, q_bias, v_bias);

    attn_kernel<<<BQ * NH, 256>>>(logit_scale);

    dim3 gp(CD / 128, MROWS / 128);
    gemm_fp16<CD, 1><<<gp, 256>>>(ao, proj_w, out, proj_b, nullptr);
}

// round 10
// speedup vs baseline: 1.2154x; 1.0282x over previous
#include <cuda_runtime.h>
#include <cuda_fp16.h>
#include <math.h>
#include <cstdint>
#include <cstddef>

#define BQ 2048
#define NT 49
#define CD 384
#define NH 12
#define HD 32
#define MROWS (BQ*NT)        // 100352
#define QKVN (3*CD)          // 1152
#define RPE 512
#define TBL 169
#define LOG_MAX_SCALE 4.60517018598809136804f

__device__ float g_qkv[(size_t)MROWS * QKVN];
__device__ float g_ao[(size_t)MROWS * CD];
__device__ float g_tab[TBL * NH];
__device__ float g_bias[NH * NT * NT];

// ---------------------------------------------------------------------------
__global__ void cpb_mlp_kernel(const float* __restrict__ w1,
                               const float* __restrict__ b1,
                               const float* __restrict__ w2)
{
    int i2 = blockIdx.x;
    int a = i2 / 13, bcol = i2 % 13;
    float vy = (float)(a - 6) * (8.0f / 6.0f);
    float vx = (float)(bcol - 6) * (8.0f / 6.0f);
    float t0 = copysignf(log2f(fabsf(vy) + 1.0f) / 3.0f, vy);
    float t1 = copysignf(log2f(fabsf(vx) + 1.0f) / 3.0f, vx);

    __shared__ float hidden[RPE];
    __shared__ float red[4];
    int tid = threadIdx.x;
    for (int r = tid; r < RPE; r += 128) {
        float hv = t0 * w1[2 * r] + t1 * w1[2 * r + 1] + b1[r];
        hidden[r] = fmaxf(hv, 0.0f);
    }
    __syncthreads();
    for (int h = 0; h < NH; h++) {
        float p = 0.0f;
        for (int r = tid; r < RPE; r += 128) p += hidden[r] * w2[h * RPE + r];
        #pragma unroll
        for (int o = 16; o > 0; o >>= 1) p += __shfl_xor_sync(0xffffffffu, p, o);
        if ((tid & 31) == 0) red[tid >> 5] = p;
        __syncthreads();
        if (tid == 0) g_tab[i2 * NH + h] = red[0] + red[1] + red[2] + red[3];
        __syncthreads();
    }
}

__global__ void bias_expand_kernel()
{
    int t = blockIdx.x * 256 + threadIdx.x;
    if (t >= NH * NT * NT) return;
    int h = t / (NT * NT);
    int ij = t % (NT * NT);
    int i = ij / NT, j = ij % NT;
    int rel = ((i / 7 - j / 7) + 6) * 13 + ((i % 7 - j % 7) + 6);
    float x = g_tab[rel * NH + h];
    g_bias[t] = 16.0f / (1.0f + __expf(-x));
}

// ---------------------------------------------------------------------------
// FP16 tensor-core GEMM (mma.sync m16n8k16, f32 accumulate), DOUBLE-BUFFERED.
// C[M,NC] = A[M,384] @ B[NC,384]^T + bias. 128x128 CTA tile, BK=32.
// ---------------------------------------------------------------------------
__device__ __forceinline__ uint32_t smem_u32(const void* p) {
    uint32_t a;
    asm("{ .reg .u64 t; cvta.to.shared.u64 t, %1; cvt.u32.u64 %0, t; }"
        : "=r"(a) : "l"(p));
    return a;
}

__device__ __forceinline__ uint2 pack4h(float4 v) {
    __half2 h0 = __floats2half2_rn(v.x, v.y);
    __half2 h1 = __floats2half2_rn(v.z, v.w);
    uint2 r;
    r.x = *(uint32_t*)&h0;
    r.y = *(uint32_t*)&h1;
    return r;
}

#define LDSM4(r0, r1, r2, r3, a) \
    asm volatile("ldmatrix.sync.aligned.m8n8.x4.shared.b16 {%0,%1,%2,%3}, [%4];" \
                 : "=r"(r0), "=r"(r1), "=r"(r2), "=r"(r3) : "r"(a))

__device__ __forceinline__ void mma_fp16(float c[4], uint32_t a0, uint32_t a1,
                                         uint32_t a2, uint32_t a3,
                                         uint32_t b0, uint32_t b1) {
    asm volatile(
        "mma.sync.aligned.m16n8k16.row.col.f32.f16.f16.f32 "
        "{%0,%1,%2,%3}, {%4,%5,%6,%7}, {%8,%9}, {%0,%1,%2,%3};"
        : "+f"(c[0]), "+f"(c[1]), "+f"(c[2]), "+f"(c[3])
        : "r"(a0), "r"(a1), "r"(a2), "r"(a3), "r"(b0), "r"(b1));
}

#define HROW 40                       // halves per smem row (32 data + 8 pad)
#define BUFB (128 * HROW * 2)         // bytes per buffer per matrix (10240)

template<int NC, int MODE>
__global__ void __launch_bounds__(256, 2) gemm_fp16(
    const float* __restrict__ A, const float* __restrict__ B,
    float* __restrict__ C,
    const float* __restrict__ bias0, const float* __restrict__ bias1)
{
    constexpr int K = 384;
    __shared__ __align__(16) uint16_t As[2][128 * HROW];
    __shared__ __align__(16) uint16_t Bs[2][128 * HROW];

    int tid = threadIdx.x;
    int lane = tid & 31, w = tid >> 5;
    int g = lane >> 2, t4 = lane & 3;
    int warp_m = (w >> 1) * 32;     // 0,32,64,96
    int warp_n = (w & 1) * 64;      // 0,64
    int m0 = blockIdx.y * 128;
    int n0 = blockIdx.x * 128;

    uint32_t as_u = smem_u32(As), bs_u = smem_u32(Bs);
    int arow = warp_m + ((lane >> 3) & 1) * 8 + (lane & 7);
    uint32_t aaddr = as_u + arow * 80 + (lane >> 4) * 16;       // + mi*1280 + kk*32 + buf*BUFB
    int brow = warp_n + ((lane >> 4) & 1) * 8 + (lane & 7);
    uint32_t baddr = bs_u + brow * 80 + ((lane >> 3) & 1) * 16; // + p*1280 + kk*32 + buf*BUFB

    int lr = tid >> 3;          // 0..31
    int lc = (tid & 7) * 4;     // 0..28

    const float* Ap = A + (size_t)(m0 + lr) * K + lc;
    const float* Bp = B + (size_t)(n0 + lr) * K + lc;

    float acc[2][8][4];
    #pragma unroll
    for (int mi = 0; mi < 2; mi++)
        #pragma unroll
        for (int ni = 0; ni < 8; ni++)
            #pragma unroll
            for (int q = 0; q < 4; q++) acc[mi][ni][q] = 0.0f;

    uint2 ra[4], rb[4];
    // prologue: stage 0 -> buf 0
    #pragma unroll
    for (int p = 0; p < 4; p++) {
        ra[p] = pack4h(*(const float4*)(Ap + (size_t)(32 * p) * K));
        rb[p] = pack4h(*(const float4*)(Bp + (size_t)(32 * p) * K));
    }
    #pragma unroll
    for (int p = 0; p < 4; p++) {
        int row = lr + 32 * p;
        *(uint2*)(As[0] + row * HROW + lc) = ra[p];
        *(uint2*)(Bs[0] + row * HROW + lc) = rb[p];
    }
    __syncthreads();

    int buf = 0;
    for (int k0 = 0; k0 < K; k0 += 32, buf ^= 1) {
        bool more = (k0 + 32 < K);
        if (more) {
            #pragma unroll
            for (int p = 0; p < 4; p++) {
                ra[p] = pack4h(*(const float4*)(Ap + (size_t)(32 * p) * K + (k0 + 32)));
                rb[p] = pack4h(*(const float4*)(Bp + (size_t)(32 * p) * K + (k0 + 32)));
            }
        }

        uint32_t ab = aaddr + buf * BUFB;
        uint32_t bb = baddr + buf * BUFB;
        #pragma unroll
        for (int kk = 0; kk < 2; kk++) {          // two k16 steps per stage
            uint32_t kb = kk * 32;                // byte offset (16 halves)
            uint32_t af[2][4], bq[4][4];
            #pragma unroll
            for (int mi = 0; mi < 2; mi++)
                LDSM4(af[mi][0], af[mi][1], af[mi][2], af[mi][3],
                      ab + mi * 1280 + kb);
            #pragma unroll
            for (int p = 0; p < 4; p++)
                LDSM4(bq[p][0], bq[p][1], bq[p][2], bq[p][3],
                      bb + p * 1280 + kb);
            #pragma unroll
            for (int mi = 0; mi < 2; mi++)
                #pragma unroll
                for (int ni = 0; ni < 8; ni++) {
                    int p = ni >> 1, hsel = (ni & 1) * 2;
                    mma_fp16(acc[mi][ni], af[mi][0], af[mi][1], af[mi][2], af[mi][3],
                             bq[p][hsel], bq[p][hsel + 1]);
                }
        }

        if (more) {
            int nb = buf ^ 1;
            #pragma unroll
            for (int p = 0; p < 4; p++) {
                int row = lr + 32 * p;
                *(uint2*)(As[nb] + row * HROW + lc) = ra[p];
                *(uint2*)(Bs[nb] + row * HROW + lc) = rb[p];
            }
        }
        __syncthreads();
    }

    #pragma unroll
    for (int ni = 0; ni < 8; ni++) {
        int col = n0 + warp_n + ni * 8 + 2 * t4;
        float bx, by;
        if (MODE == 0) {
            bx = (col < CD) ? bias0[col] : ((col < 2 * CD) ? 0.0f : bias1[col - 2 * CD]);
            int c1 = col + 1;
            by = (c1 < CD) ? bias0[c1] : ((c1 < 2 * CD) ? 0.0f : bias1[c1 - 2 * CD]);
        } else {
            bx = bias0[col]; by = bias0[col + 1];
        }
        #pragma unroll
        for (int mi = 0; mi < 2; mi++) {
            int row = m0 + warp_m + mi * 16 + g;
            float2 o0 = make_float2(acc[mi][ni][0] + bx, acc[mi][ni][1] + by);
            float2 o1 = make_float2(acc[mi][ni][2] + bx, acc[mi][ni][3] + by);
            *(float2*)(C + (size_t)row * NC + col) = o0;
            *(float2*)(C + (size_t)(row + 8) * NC + col) = o1;
        }
    }
}

// ---------------------------------------------------------------------------
// Attention (round-5 register-blocked version; best measured)
// ---------------------------------------------------------------------------
#define QKP 36
#define PSP 52

__device__ __forceinline__ float dot4(float4 a, float4 b, float acc) {
    acc = fmaf(a.x, b.x, acc); acc = fmaf(a.y, b.y, acc);
    acc = fmaf(a.z, b.z, acc); acc = fmaf(a.w, b.w, acc);
    return acc;
}

__global__ void __launch_bounds__(256, 4) attn_kernel(const float* __restrict__ logit_scale)
{
    int bh = blockIdx.x;
    int b = bh / NH, h = bh % NH;
    __shared__ float qs[NT * QKP];
    __shared__ float ks[NT * QKP];
    __shared__ float vt[HD * PSP];
    __shared__ float ps[NT * PSP];

    int tid = threadIdx.x, lane = tid & 31, warp = tid >> 5;
    float scale = __expf(fminf(logit_scale[h], LOG_MAX_SCALE));

    size_t base = (size_t)(b * NT) * QKVN + (size_t)h * HD;
    for (int idx = tid; idx < NT * 8; idx += 256) {
        int i = idx >> 3, d4 = (idx & 7) * 4;
        size_t off = base + (size_t)i * QKVN + d4;
        float4 qv = *(const float4*)(g_qkv + off);
        float4 kv = *(const float4*)(g_qkv + off + CD);
        float4 vv = *(const float4*)(g_qkv + off + 2 * CD);
        *(float4*)(qs + i * QKP + d4) = qv;
        *(float4*)(ks + i * QKP + d4) = kv;
        vt[(d4 + 0) * PSP + i] = vv.x;
        vt[(d4 + 1) * PSP + i] = vv.y;
        vt[(d4 + 2) * PSP + i] = vv.z;
        vt[(d4 + 3) * PSP + i] = vv.w;
    }
    __syncthreads();

    for (int i = warp; i < NT; i += 8) {
        float qv = qs[i * QKP + lane];
        float s = qv * qv;
        #pragma unroll
        for (int o = 16; o > 0; o >>= 1) s += __shfl_xor_sync(0xffffffffu, s, o);
        qs[i * QKP + lane] = qv * (scale / (sqrtf(s) + 1e-12f));
        float kv = ks[i * QKP + lane];
        float s2 = kv * kv;
        #pragma unroll
        for (int o = 16; o > 0; o >>= 1) s2 += __shfl_xor_sync(0xffffffffu, s2, o);
        ks[i * QKP + lane] = kv / (sqrtf(s2) + 1e-12f);
    }
    __syncthreads();

    int j1 = (lane < 17) ? (lane + 32) : 0;
    float d00[4], d01[4], d10[4], d11[4];
    #pragma unroll
    for (int p = 0; p < 4; p++) { d00[p] = d01[p] = d10[p] = d11[p] = 0.0f; }

    #pragma unroll
    for (int q8 = 0; q8 < HD; q8 += 8) {
        float4 k0a = *(const float4*)(ks + lane * QKP + q8);
        float4 k0b = *(const float4*)(ks + lane * QKP + q8 + 4);
        float4 k1a = *(const float4*)(ks + j1 * QKP + q8);
        float4 k1b = *(const float4*)(ks + j1 * QKP + q8 + 4);
        #pragma unroll
        for (int p = 0; p < 4; p++) {
            int i0 = warp * 2 + p * 16;
            if (i0 >= NT) continue;
            int i1 = (i0 + 1 < NT) ? (i0 + 1) : i0;
            float4 q0a = *(const float4*)(qs + i0 * QKP + q8);
            float4 q0b = *(const float4*)(qs + i0 * QKP + q8 + 4);
            float4 q1a = *(const float4*)(qs + i1 * QKP + q8);
            float4 q1b = *(const float4*)(qs + i1 * QKP + q8 + 4);
            d00[p] = dot4(q0b, k0b, dot4(q0a, k0a, d00[p]));
            d01[p] = dot4(q0b, k1b, dot4(q0a, k1a, d01[p]));
            d10[p] = dot4(q1b, k0b, dot4(q1a, k0a, d10[p]));
            d11[p] = dot4(q1b, k1b, dot4(q1a, k1a, d11[p]));
        }
    }

    const float* bias_h = g_bias + h * NT * NT;
    #pragma unroll
    for (int p = 0; p < 4; p++) {
        int i0 = warp * 2 + p * 16;
        if (i0 >= NT) continue;
        bool has1 = (i0 + 1 < NT);
        {
            float s0 = d00[p] + __ldg(bias_h + i0 * NT + lane);
            float s1 = (lane < 17) ? (d01[p] + __ldg(bias_h + i0 * NT + 32 + lane)) : -INFINITY;
            float m = fmaxf(s0, s1);
            #pragma unroll
            for (int o = 16; o > 0; o >>= 1) m = fmaxf(m, __shfl_xor_sync(0xffffffffu, m, o));
            float e0 = __expf(s0 - m);
            float e1 = (lane < 17) ? __expf(s1 - m) : 0.0f;
            float sum = e0 + e1;
            #pragma unroll
            for (int o = 16; o > 0; o >>= 1) sum += __shfl_xor_sync(0xffffffffu, sum, o);
            float inv = __fdividef(1.0f, sum);
            ps[i0 * PSP + lane] = e0 * inv;
            if (lane < 17) ps[i0 * PSP + 32 + lane] = e1 * inv;
        }
        if (has1) {
            int i1 = i0 + 1;
            float s0 = d10[p] + __ldg(bias_h + i1 * NT + lane);
            float s1 = (lane < 17) ? (d11[p] + __ldg(bias_h + i1 * NT + 32 + lane)) : -INFINITY;
            float m = fmaxf(s0, s1);
            #pragma unroll
            for (int o = 16; o > 0; o >>= 1) m = fmaxf(m, __shfl_xor_sync(0xffffffffu, m, o));
            float e0 = __expf(s0 - m);
            float e1 = (lane < 17) ? __expf(s1 - m) : 0.0f;
            float sum = e0 + e1;
            #pragma unroll
            for (int o = 16; o > 0; o >>= 1) sum += __shfl_xor_sync(0xffffffffu, sum, o);
            float inv = __fdividef(1.0f, sum);
            ps[i1 * PSP + lane] = e0 * inv;
            if (lane < 17) ps[i1 * PSP + 32 + lane] = e1 * inv;
        }
    }
    __syncthreads();

    float a0[4], a1[4];
    #pragma unroll
    for (int p = 0; p < 4; p++) { a0[p] = a1[p] = 0.0f; }

    #pragma unroll
    for (int jc = 0; jc < 48; jc += 16) {
        float4 v0 = *(const float4*)(vt + lane * PSP + jc);
        float4 v1 = *(const float4*)(vt + lane * PSP + jc + 4);
        float4 v2 = *(const float4*)(vt + lane * PSP + jc + 8);
        float4 v3 = *(const float4*)(vt + lane * PSP + jc + 12);
        #pragma unroll
        for (int p = 0; p < 4; p++) {
            int i0 = warp * 2 + p * 16;
            if (i0 >= NT) continue;
            int i1 = (i0 + 1 < NT) ? (i0 + 1) : i0;
            float4 p00 = *(const float4*)(ps + i0 * PSP + jc);
            float4 p01 = *(const float4*)(ps + i0 * PSP + jc + 4);
            float4 p02 = *(const float4*)(ps + i0 * PSP + jc + 8);
            float4 p03 = *(const float4*)(ps + i0 * PSP + jc + 12);
            a0[p] = dot4(p03, v3, dot4(p02, v2, dot4(p01, v1, dot4(p00, v0, a0[p]))));
            float4 p10 = *(const float4*)(ps + i1 * PSP + jc);
            float4 p11 = *(const float4*)(ps + i1 * PSP + jc + 4);
            float4 p12 = *(const float4*)(ps + i1 * PSP + jc + 8);
            float4 p13 = *(const float4*)(ps + i1 * PSP + jc + 12);
            a1[p] = dot4(p13, v3, dot4(p12, v2, dot4(p11, v1, dot4(p10, v0, a1[p]))));
        }
    }
    {
        float vv = vt[lane * PSP + 48];
        #pragma unroll
        for (int p = 0; p < 4; p++) {
            int i0 = warp * 2 + p * 16;
            if (i0 >= NT) continue;
            bool has1 = (i0 + 1 < NT);
            int i1 = has1 ? (i0 + 1) : i0;
            a0[p] = fmaf(ps[i0 * PSP + 48], vv, a0[p]);
            a1[p] = fmaf(ps[i1 * PSP + 48], vv, a1[p]);
            g_ao[(size_t)(b * NT + i0) * CD + h * HD + lane] = a0[p];
            if (has1)
                g_ao[(size_t)(b * NT + i1) * CD + h * HD + lane] = a1[p];
        }
    }
}

// ---------------------------------------------------------------------------
extern "C" void kernel_launch(void* const* d_in, const int* in_sizes, int n_in,
                              void* d_out, int out_size)
{
    const float* x           = (const float*)d_in[0];
    const float* qkv_w       = (const float*)d_in[1];
    const float* q_bias      = (const float*)d_in[2];
    const float* v_bias      = (const float*)d_in[3];
    const float* logit_scale = (const float*)d_in[4];
    const float* cpb_w1      = (const float*)d_in[5];
    const float* cpb_b1      = (const float*)d_in[6];
    const float* cpb_w2      = (const float*)d_in[7];
    const float* proj_w      = (const float*)d_in[8];
    const float* proj_b      = (const float*)d_in[9];
    float* out = (float*)d_out;

    void* p;
    cudaGetSymbolAddress(&p, g_qkv); float* qkv = (float*)p;
    cudaGetSymbolAddress(&p, g_ao);  float* ao  = (float*)p;

    cpb_mlp_kernel<<<TBL, 128>>>(cpb_w1, cpb_b1, cpb_w2);
    bias_expand_kernel<<<(NH * NT * NT + 255) / 256, 256>>>();

    dim3 gq(QKVN / 128, MROWS / 128);
    gemm_fp16<QKVN, 0><<<gq, 256>>>(x, qkv_w, qkv, q_bias, v_bias);

    attn_kernel<<<BQ * NH, 256>>>(logit_scale);

    dim3 gp(CD / 128, MROWS / 128);
    gemm_fp16<CD, 1><<<gp, 256>>>(ao, proj_w, out, proj_b, nullptr);
}

// round 11
// speedup vs baseline: 1.3387x; 1.1014x over previous
#include <cuda_runtime.h>
#include <cuda_fp16.h>
#include <math.h>
#include <cstdint>
#include <cstddef>

#define BQ 2048
#define NT 49
#define CD 384
#define NH 12
#define HD 32
#define MROWS (BQ*NT)        // 100352
#define QKVN (3*CD)          // 1152
#define RPE 512
#define TBL 169
#define LOG_MAX_SCALE 4.60517018598809136804f

__device__ float g_qkv[(size_t)MROWS * QKVN];
__device__ float g_ao[(size_t)MROWS * CD];
__device__ float g_tab[TBL * NH];
__device__ float g_bias[NH * NT * NT];

// ---------------------------------------------------------------------------
__global__ void cpb_mlp_kernel(const float* __restrict__ w1,
                               const float* __restrict__ b1,
                               const float* __restrict__ w2)
{
    int i2 = blockIdx.x;
    int a = i2 / 13, bcol = i2 % 13;
    float vy = (float)(a - 6) * (8.0f / 6.0f);
    float vx = (float)(bcol - 6) * (8.0f / 6.0f);
    float t0 = copysignf(log2f(fabsf(vy) + 1.0f) / 3.0f, vy);
    float t1 = copysignf(log2f(fabsf(vx) + 1.0f) / 3.0f, vx);

    __shared__ float hidden[RPE];
    __shared__ float red[4];
    int tid = threadIdx.x;
    for (int r = tid; r < RPE; r += 128) {
        float hv = t0 * w1[2 * r] + t1 * w1[2 * r + 1] + b1[r];
        hidden[r] = fmaxf(hv, 0.0f);
    }
    __syncthreads();
    for (int h = 0; h < NH; h++) {
        float p = 0.0f;
        for (int r = tid; r < RPE; r += 128) p += hidden[r] * w2[h * RPE + r];
        #pragma unroll
        for (int o = 16; o > 0; o >>= 1) p += __shfl_xor_sync(0xffffffffu, p, o);
        if ((tid & 31) == 0) red[tid >> 5] = p;
        __syncthreads();
        if (tid == 0) g_tab[i2 * NH + h] = red[0] + red[1] + red[2] + red[3];
        __syncthreads();
    }
}

__global__ void bias_expand_kernel()
{
    int t = blockIdx.x * 256 + threadIdx.x;
    if (t >= NH * NT * NT) return;
    int h = t / (NT * NT);
    int ij = t % (NT * NT);
    int i = ij / NT, j = ij % NT;
    int rel = ((i / 7 - j / 7) + 6) * 13 + ((i % 7 - j % 7) + 6);
    float x = g_tab[rel * NH + h];
    g_bias[t] = 16.0f / (1.0f + __expf(-x));
}

// ---------------------------------------------------------------------------
// common MMA helpers
// ---------------------------------------------------------------------------
__device__ __forceinline__ uint32_t smem_u32(const void* p) {
    uint32_t a;
    asm("{ .reg .u64 t; cvta.to.shared.u64 t, %1; cvt.u32.u64 %0, t; }"
        : "=r"(a) : "l"(p));
    return a;
}

__device__ __forceinline__ uint2 pack4h(float4 v) {
    __half2 h0 = __floats2half2_rn(v.x, v.y);
    __half2 h1 = __floats2half2_rn(v.z, v.w);
    uint2 r;
    r.x = *(uint32_t*)&h0;
    r.y = *(uint32_t*)&h1;
    return r;
}

#define LDSM4(r0, r1, r2, r3, a) \
    asm volatile("ldmatrix.sync.aligned.m8n8.x4.shared.b16 {%0,%1,%2,%3}, [%4];" \
                 : "=r"(r0), "=r"(r1), "=r"(r2), "=r"(r3) : "r"(a))

__device__ __forceinline__ void mma_fp16(float c[4], uint32_t a0, uint32_t a1,
                                         uint32_t a2, uint32_t a3,
                                         uint32_t b0, uint32_t b1) {
    asm volatile(
        "mma.sync.aligned.m16n8k16.row.col.f32.f16.f16.f32 "
        "{%0,%1,%2,%3}, {%4,%5,%6,%7}, {%8,%9}, {%0,%1,%2,%3};"
        : "+f"(c[0]), "+f"(c[1]), "+f"(c[2]), "+f"(c[3])
        : "r"(a0), "r"(a1), "r"(a2), "r"(a3), "r"(b0), "r"(b1));
}

// split a float pair into (hi fp16 pair, lo fp16 residual pair)
__device__ __forceinline__ void pack_hl(float f0, float f1, uint32_t& hi, uint32_t& lo) {
    __half h0 = __float2half_rn(f0), h1 = __float2half_rn(f1);
    __half l0 = __float2half_rn(f0 - __half2float(h0));
    __half l1 = __float2half_rn(f1 - __half2float(h1));
    hi = (uint32_t)(*(uint16_t*)&h0) | ((uint32_t)(*(uint16_t*)&h1) << 16);
    lo = (uint32_t)(*(uint16_t*)&l0) | ((uint32_t)(*(uint16_t*)&l1) << 16);
}

__device__ __forceinline__ void split_store(uint16_t* hi_p, uint16_t* lo_p, float f) {
    __half h = __float2half_rn(f);
    __half l = __float2half_rn(f - __half2float(h));
    *hi_p = *(uint16_t*)&h;
    *lo_p = *(uint16_t*)&l;
}

// ---------------------------------------------------------------------------
// FP16 tensor-core GEMM (round-10, double-buffered) — unchanged
// ---------------------------------------------------------------------------
#define HROW 40
#define BUFB (128 * HROW * 2)

template<int NC, int MODE>
__global__ void __launch_bounds__(256, 2) gemm_fp16(
    const float* __restrict__ A, const float* __restrict__ B,
    float* __restrict__ C,
    const float* __restrict__ bias0, const float* __restrict__ bias1)
{
    constexpr int K = 384;
    __shared__ __align__(16) uint16_t As[2][128 * HROW];
    __shared__ __align__(16) uint16_t Bs[2][128 * HROW];

    int tid = threadIdx.x;
    int lane = tid & 31, w = tid >> 5;
    int g = lane >> 2, t4 = lane & 3;
    int warp_m = (w >> 1) * 32;
    int warp_n = (w & 1) * 64;
    int m0 = blockIdx.y * 128;
    int n0 = blockIdx.x * 128;

    uint32_t as_u = smem_u32(As), bs_u = smem_u32(Bs);
    int arow = warp_m + ((lane >> 3) & 1) * 8 + (lane & 7);
    uint32_t aaddr = as_u + arow * 80 + (lane >> 4) * 16;
    int brow = warp_n + ((lane >> 4) & 1) * 8 + (lane & 7);
    uint32_t baddr = bs_u + brow * 80 + ((lane >> 3) & 1) * 16;

    int lr = tid >> 3;
    int lc = (tid & 7) * 4;

    const float* Ap = A + (size_t)(m0 + lr) * K + lc;
    const float* Bp = B + (size_t)(n0 + lr) * K + lc;

    float acc[2][8][4];
    #pragma unroll
    for (int mi = 0; mi < 2; mi++)
        #pragma unroll
        for (int ni = 0; ni < 8; ni++)
            #pragma unroll
            for (int q = 0; q < 4; q++) acc[mi][ni][q] = 0.0f;

    uint2 ra[4], rb[4];
    #pragma unroll
    for (int p = 0; p < 4; p++) {
        ra[p] = pack4h(*(const float4*)(Ap + (size_t)(32 * p) * K));
        rb[p] = pack4h(*(const float4*)(Bp + (size_t)(32 * p) * K));
    }
    #pragma unroll
    for (int p = 0; p < 4; p++) {
        int row = lr + 32 * p;
        *(uint2*)(As[0] + row * HROW + lc) = ra[p];
        *(uint2*)(Bs[0] + row * HROW + lc) = rb[p];
    }
    __syncthreads();

    int buf = 0;
    for (int k0 = 0; k0 < K; k0 += 32, buf ^= 1) {
        bool more = (k0 + 32 < K);
        if (more) {
            #pragma unroll
            for (int p = 0; p < 4; p++) {
                ra[p] = pack4h(*(const float4*)(Ap + (size_t)(32 * p) * K + (k0 + 32)));
                rb[p] = pack4h(*(const float4*)(Bp + (size_t)(32 * p) * K + (k0 + 32)));
            }
        }

        uint32_t ab = aaddr + buf * BUFB;
        uint32_t bb = baddr + buf * BUFB;
        #pragma unroll
        for (int kk = 0; kk < 2; kk++) {
            uint32_t kb = kk * 32;
            uint32_t af[2][4], bq[4][4];
            #pragma unroll
            for (int mi = 0; mi < 2; mi++)
                LDSM4(af[mi][0], af[mi][1], af[mi][2], af[mi][3],
                      ab + mi * 1280 + kb);
            #pragma unroll
            for (int p = 0; p < 4; p++)
                LDSM4(bq[p][0], bq[p][1], bq[p][2], bq[p][3],
                      bb + p * 1280 + kb);
            #pragma unroll
            for (int mi = 0; mi < 2; mi++)
                #pragma unroll
                for (int ni = 0; ni < 8; ni++) {
                    int p = ni >> 1, hsel = (ni & 1) * 2;
                    mma_fp16(acc[mi][ni], af[mi][0], af[mi][1], af[mi][2], af[mi][3],
                             bq[p][hsel], bq[p][hsel + 1]);
                }
        }

        if (more) {
            int nb = buf ^ 1;
            #pragma unroll
            for (int p = 0; p < 4; p++) {
                int row = lr + 32 * p;
                *(uint2*)(As[nb] + row * HROW + lc) = ra[p];
                *(uint2*)(Bs[nb] + row * HROW + lc) = rb[p];
            }
        }
        __syncthreads();
    }

    #pragma unroll
    for (int ni = 0; ni < 8; ni++) {
        int col = n0 + warp_n + ni * 8 + 2 * t4;
        float bx, by;
        if (MODE == 0) {
            bx = (col < CD) ? bias0[col] : ((col < 2 * CD) ? 0.0f : bias1[col - 2 * CD]);
            int c1 = col + 1;
            by = (c1 < CD) ? bias0[c1] : ((c1 < 2 * CD) ? 0.0f : bias1[c1 - 2 * CD]);
        } else {
            bx = bias0[col]; by = bias0[col + 1];
        }
        #pragma unroll
        for (int mi = 0; mi < 2; mi++) {
            int row = m0 + warp_m + mi * 16 + g;
            float2 o0 = make_float2(acc[mi][ni][0] + bx, acc[mi][ni][1] + by);
            float2 o1 = make_float2(acc[mi][ni][2] + bx, acc[mi][ni][3] + by);
            *(float2*)(C + (size_t)row * NC + col) = o0;
            *(float2*)(C + (size_t)(row + 8) * NC + col) = o1;
        }
    }
}

// ---------------------------------------------------------------------------
// MMA attention: one CTA per (window, head), 128 threads / 4 warps.
// fp16 hi/lo split arithmetic (exact): QK = qh*kh + qh*kl + ql*kh,
// PV = ph*vh + ph*vl + pl*vh. P stays register-resident (C->A repack).
// ---------------------------------------------------------------------------
#define AQ_STR 40    // halves per row of q/k smem (32 + 8 pad), 80 B
#define AV_STR 72    // halves per row of v^T smem (64 + 8 pad), 144 B
#define QK_BUF (64 * AQ_STR)       // halves per split buffer
#define QK_BUFB (QK_BUF * 2)       // 5120 bytes
#define VT_BUF (32 * AV_STR)
#define VT_BUFB (VT_BUF * 2)       // 4608 bytes

__global__ void __launch_bounds__(128) attn_mma(const float* __restrict__ logit_scale)
{
    __shared__ __align__(16) uint16_t qs[2][QK_BUF];
    __shared__ __align__(16) uint16_t ks[2][QK_BUF];
    __shared__ __align__(16) uint16_t vts[2][VT_BUF];

    int bh = blockIdx.x;
    int b = bh / NH, h = bh % NH;
    int tid = threadIdx.x, lane = tid & 31, warp = tid >> 5;
    int g = lane >> 2, t4 = lane & 3;
    float scale = __expf(fminf(logit_scale[h], LOG_MAX_SCALE));

    // zero all smem (covers pad rows/cols)
    {
        uint4 z = make_uint4(0, 0, 0, 0);
        uint4* q4 = (uint4*)qs;   // 2*QK_BUF*2/16 = 1280 uint4
        uint4* k4 = (uint4*)ks;
        uint4* v4 = (uint4*)vts;  // 1152/2... 2*VT_BUF*2/16 = 576
        for (int i = tid; i < 2 * QK_BUF / 8; i += 128) { q4[i] = z; k4[i] = z; }
        for (int i = tid; i < 2 * VT_BUF / 8; i += 128) v4[i] = z;
    }
    __syncthreads();

    // load + normalize + split. warp handles rows warp, warp+4, ...
    for (int i = warp; i < NT; i += 4) {
        size_t off = (size_t)(b * NT + i) * QKVN + (size_t)h * HD + lane;
        float qv = g_qkv[off];
        float kv = g_qkv[off + CD];
        float vv = g_qkv[off + 2 * CD];
        float sq = qv * qv;
        #pragma unroll
        for (int o = 16; o > 0; o >>= 1) sq += __shfl_xor_sync(0xffffffffu, sq, o);
        float qn = qv * (scale / (sqrtf(sq) + 1e-12f));
        float sk = kv * kv;
        #pragma unroll
        for (int o = 16; o > 0; o >>= 1) sk += __shfl_xor_sync(0xffffffffu, sk, o);
        float kn = kv / (sqrtf(sk) + 1e-12f);

        split_store(&qs[0][i * AQ_STR + lane], &qs[1][i * AQ_STR + lane], qn);
        split_store(&ks[0][i * AQ_STR + lane], &ks[1][i * AQ_STR + lane], kn);
        split_store(&vts[0][lane * AV_STR + i], &vts[1][lane * AV_STR + i], vv);
    }
    __syncthreads();

    int r0 = warp * 16;
    // ---- QK^T: acc[nt][q] covers rows {r0+g, r0+g+8}, cols nt*8 + 2*t4 {+0,+1}
    float acc[8][4];
    #pragma unroll
    for (int nt = 0; nt < 8; nt++)
        #pragma unroll
        for (int q = 0; q < 4; q++) acc[nt][q] = 0.0f;

    uint32_t qaddr = smem_u32(qs) + (r0 + ((lane >> 3) & 1) * 8 + (lane & 7)) * 80
                   + (lane >> 4) * 16;
    uint32_t kaddr = smem_u32(ks) + (((lane >> 4) & 1) * 8 + (lane & 7)) * 80
                   + ((lane >> 3) & 1) * 16;

    #pragma unroll
    for (int ki = 0; ki < 2; ki++) {
        uint32_t ah[4], al[4];
        LDSM4(ah[0], ah[1], ah[2], ah[3], qaddr + ki * 32);
        LDSM4(al[0], al[1], al[2], al[3], qaddr + QK_BUFB + ki * 32);
        #pragma unroll
        for (int ntp = 0; ntp < 4; ntp++) {
            uint32_t bh_[4], bl_[4];
            LDSM4(bh_[0], bh_[1], bh_[2], bh_[3], kaddr + ntp * 16 * 80 + ki * 32);
            LDSM4(bl_[0], bl_[1], bl_[2], bl_[3], kaddr + QK_BUFB + ntp * 16 * 80 + ki * 32);
            #pragma unroll
            for (int sub = 0; sub < 2; sub++) {
                int nt = ntp * 2 + sub;
                uint32_t b0h = bh_[sub * 2], b1h = bh_[sub * 2 + 1];
                uint32_t b0l = bl_[sub * 2], b1l = bl_[sub * 2 + 1];
                mma_fp16(acc[nt], ah[0], ah[1], ah[2], ah[3], b0h, b1h);
                mma_fp16(acc[nt], ah[0], ah[1], ah[2], ah[3], b0l, b1l);
                mma_fp16(acc[nt], al[0], al[1], al[2], al[3], b0h, b1h);
            }
        }
    }

    // ---- bias + mask + softmax (rows rA = r0+g, rB = rA+8)
    int rA = r0 + g, rB = rA + 8;
    int rAc = (rA < NT) ? rA : NT - 1;
    int rBc = (rB < NT) ? rB : NT - 1;
    const float* bias_h = g_bias + h * NT * NT;
    float mA = -1e30f, mB = -1e30f;
    #pragma unroll
    for (int nt = 0; nt < 8; nt++) {
        int c0 = nt * 8 + t4 * 2;
        int c0c = (c0 < NT) ? c0 : NT - 1;
        int c1c = (c0 + 1 < NT) ? c0 + 1 : NT - 1;
        float bA0 = __ldg(bias_h + rAc * NT + c0c);
        float bA1 = __ldg(bias_h + rAc * NT + c1c);
        float bB0 = __ldg(bias_h + rBc * NT + c0c);
        float bB1 = __ldg(bias_h + rBc * NT + c1c);
        acc[nt][0] = (c0 < NT) ? acc[nt][0] + bA0 : -1e30f;
        acc[nt][1] = (c0 + 1 < NT) ? acc[nt][1] + bA1 : -1e30f;
        acc[nt][2] = (c0 < NT) ? acc[nt][2] + bB0 : -1e30f;
        acc[nt][3] = (c0 + 1 < NT) ? acc[nt][3] + bB1 : -1e30f;
        mA = fmaxf(mA, fmaxf(acc[nt][0], acc[nt][1]));
        mB = fmaxf(mB, fmaxf(acc[nt][2], acc[nt][3]));
    }
    mA = fmaxf(mA, __shfl_xor_sync(0xffffffffu, mA, 1));
    mA = fmaxf(mA, __shfl_xor_sync(0xffffffffu, mA, 2));
    mB = fmaxf(mB, __shfl_xor_sync(0xffffffffu, mB, 1));
    mB = fmaxf(mB, __shfl_xor_sync(0xffffffffu, mB, 2));

    float sumA = 0.0f, sumB = 0.0f;
    #pragma unroll
    for (int nt = 0; nt < 8; nt++) {
        float p0 = __expf(acc[nt][0] - mA);
        float p1 = __expf(acc[nt][1] - mA);
        float p2 = __expf(acc[nt][2] - mB);
        float p3 = __expf(acc[nt][3] - mB);
        acc[nt][0] = p0; acc[nt][1] = p1; acc[nt][2] = p2; acc[nt][3] = p3;
        sumA += p0 + p1;
        sumB += p2 + p3;
    }
    sumA += __shfl_xor_sync(0xffffffffu, sumA, 1);
    sumA += __shfl_xor_sync(0xffffffffu, sumA, 2);
    sumB += __shfl_xor_sync(0xffffffffu, sumB, 1);
    sumB += __shfl_xor_sync(0xffffffffu, sumB, 2);
    float invA = __fdividef(1.0f, sumA);
    float invB = __fdividef(1.0f, sumB);

    // ---- PV: O[16 x 32] per warp; P repacked from acc, V from transposed smem
    float o[4][4];
    #pragma unroll
    for (int nd = 0; nd < 4; nd++)
        #pragma unroll
        for (int q = 0; q < 4; q++) o[nd][q] = 0.0f;

    uint32_t vaddr = smem_u32(vts) + (((lane >> 4) & 1) * 8 + (lane & 7)) * 144
                   + ((lane >> 3) & 1) * 16;

    #pragma unroll
    for (int js = 0; js < 4; js++) {
        uint32_t ph[4], pl[4];
        pack_hl(acc[2 * js][0],     acc[2 * js][1],     ph[0], pl[0]);
        pack_hl(acc[2 * js][2],     acc[2 * js][3],     ph[1], pl[1]);
        pack_hl(acc[2 * js + 1][0], acc[2 * js + 1][1], ph[2], pl[2]);
        pack_hl(acc[2 * js + 1][2], acc[2 * js + 1][3], ph[3], pl[3]);
        #pragma unroll
        for (int ndp = 0; ndp < 2; ndp++) {
            uint32_t vh_[4], vl_[4];
            LDSM4(vh_[0], vh_[1], vh_[2], vh_[3],
                  vaddr + ndp * 16 * 144 + js * 32);
            LDSM4(vl_[0], vl_[1], vl_[2], vl_[3],
                  vaddr + VT_BUFB + ndp * 16 * 144 + js * 32);
            #pragma unroll
            for (int sub = 0; sub < 2; sub++) {
                int nd = ndp * 2 + sub;
                uint32_t b0h = vh_[sub * 2], b1h = vh_[sub * 2 + 1];
                uint32_t b0l = vl_[sub * 2], b1l = vl_[sub * 2 + 1];
                mma_fp16(o[nd], ph[0], ph[1], ph[2], ph[3], b0h, b1h);
                mma_fp16(o[nd], ph[0], ph[1], ph[2], ph[3], b0l, b1l);
                mma_fp16(o[nd], pl[0], pl[1], pl[2], pl[3], b0h, b1h);
            }
        }
    }

    // ---- store
    if (rA < NT) {
        float* dst = g_ao + (size_t)(b * NT + rA) * CD + h * HD;
        #pragma unroll
        for (int nd = 0; nd < 4; nd++) {
            int d = nd * 8 + t4 * 2;
            *(float2*)(dst + d) = make_float2(o[nd][0] * invA, o[nd][1] * invA);
        }
    }
    if (rB < NT) {
        float* dst = g_ao + (size_t)(b * NT + rB) * CD + h * HD;
        #pragma unroll
        for (int nd = 0; nd < 4; nd++) {
            int d = nd * 8 + t4 * 2;
            *(float2*)(dst + d) = make_float2(o[nd][2] * invB, o[nd][3] * invB);
        }
    }
}

// ---------------------------------------------------------------------------
extern "C" void kernel_launch(void* const* d_in, const int* in_sizes, int n_in,
                              void* d_out, int out_size)
{
    const float* x           = (const float*)d_in[0];
    const float* qkv_w       = (const float*)d_in[1];
    const float* q_bias      = (const float*)d_in[2];
    const float* v_bias      = (const float*)d_in[3];
    const float* logit_scale = (const float*)d_in[4];
    const float* cpb_w1      = (const float*)d_in[5];
    const float* cpb_b1      = (const float*)d_in[6];
    const float* cpb_w2      = (const float*)d_in[7];
    const float* proj_w      = (const float*)d_in[8];
    const float* proj_b      = (const float*)d_in[9];
    float* out = (float*)d_out;

    void* p;
    cudaGetSymbolAddress(&p, g_qkv); float* qkv = (float*)p;
    cudaGetSymbolAddress(&p, g_ao);  float* ao  = (float*)p;

    cpb_mlp_kernel<<<TBL, 128>>>(cpb_w1, cpb_b1, cpb_w2);
    bias_expand_kernel<<<(NH * NT * NT + 255) / 256, 256>>>();

    dim3 gq(QKVN / 128, MROWS / 128);
    gemm_fp16<QKVN, 0><<<gq, 256>>>(x, qkv_w, qkv, q_bias, v_bias);

    attn_mma<<<BQ * NH, 128>>>(logit_scale);

    dim3 gp(CD / 128, MROWS / 128);
    gemm_fp16<CD, 1><<<gp, 256>>>(ao, proj_w, out, proj_b, nullptr);
}